// round 2
// baseline (speedup 1.0000x reference)
#include <cuda_runtime.h>
#include <math.h>

#define NV    65536
#define NV4   (NV*4)
#define ITERS 40
#define NF    130050
#define NBLK  128
#define NTHR  512
#define NSYNC 96

// ---- device scratch (no allocations allowed) ----
__device__ __align__(16) float    g_W[NV*7];              // aggregated COO weights (slot 0 = diag)
__device__ __align__(16) float4   g_Z[NV4];               // Z = Minv*R  (stencil operand)
__device__ __align__(16) float    g_denom[ITERS*16];
__device__ __align__(16) float    g_rz[(ITERS+1)*16];
__device__ unsigned               g_cnt[NSYNC];

// ---------------- helpers ----------------
__device__ __forceinline__ float4 f4add(float4 a, float4 b){ return make_float4(a.x+b.x,a.y+b.y,a.z+b.z,a.w+b.w); }
__device__ __forceinline__ float4 f4mul(float4 a, float4 b){ return make_float4(a.x*b.x,a.y*b.y,a.z*b.z,a.w*b.w); }
__device__ __forceinline__ float4 f4fma(float4 a, float4 b, float4 c){
    return make_float4(fmaf(a.x,b.x,c.x), fmaf(a.y,b.y,c.y), fmaf(a.z,b.z,c.z), fmaf(a.w,b.w,c.w));
}
__device__ __forceinline__ float4 f4fmas(float s, float4 b, float4 c){
    return make_float4(fmaf(s,b.x,c.x), fmaf(s,b.y,c.y), fmaf(s,b.z,c.z), fmaf(s,b.w,c.w));
}
__device__ __forceinline__ float4 f4scale(float s, float4 a){ return make_float4(s*a.x,s*a.y,s*a.z,s*a.w); }
__device__ __forceinline__ float4 f4div_guard(float4 n, float4 d){
    return make_float4(n.x/fmaxf(d.x,1e-30f), n.y/fmaxf(d.y,1e-30f),
                       n.z/fmaxf(d.z,1e-30f), n.w/fmaxf(d.w,1e-30f));
}

// software grid barrier: per-index monotone counters, zeroed each launch by zero_k
__device__ __forceinline__ void gsync(int idx){
    __syncthreads();
    if (threadIdx.x == 0){
        __threadfence();
        atomicAdd(&g_cnt[idx], 1u);
        while (*(volatile unsigned*)&g_cnt[idx] < (unsigned)NBLK) { }
        __threadfence();
    }
    __syncthreads();
}

// block reduce of 16 per-thread partials (float4 s[4]) into dst[0..15] (atomic)
__device__ __forceinline__ void reduce16(float4* s, float* dst){
    #pragma unroll
    for (int m = 16; m > 0; m >>= 1){
        #pragma unroll
        for (int j = 0; j < 4; j++){
            s[j].x += __shfl_xor_sync(0xffffffffu, s[j].x, m);
            s[j].y += __shfl_xor_sync(0xffffffffu, s[j].y, m);
            s[j].z += __shfl_xor_sync(0xffffffffu, s[j].z, m);
            s[j].w += __shfl_xor_sync(0xffffffffu, s[j].w, m);
        }
    }
    __shared__ float sm[16][16];
    int lane = threadIdx.x & 31, wid = threadIdx.x >> 5;
    if (lane == 0){
        #pragma unroll
        for (int j = 0; j < 4; j++){
            sm[wid][j*4+0] = s[j].x; sm[wid][j*4+1] = s[j].y;
            sm[wid][j*4+2] = s[j].z; sm[wid][j*4+3] = s[j].w;
        }
    }
    __syncthreads();
    if (threadIdx.x < 16){
        float acc = 0.f;
        #pragma unroll
        for (int w = 0; w < 16; w++) acc += sm[w][threadIdx.x];
        atomicAdd(&dst[threadIdx.x], acc);
    }
    // next smem reuse is separated by gsync's __syncthreads
}

// ---------------- setup kernels ----------------
__global__ void zero_k(){
    int tid = blockIdx.x * blockDim.x + threadIdx.x;   // grid sized to exactly NV*7
    g_W[tid] = 0.f;
    if (tid < ITERS*16)     g_denom[tid] = 0.f;
    if (tid < (ITERS+1)*16) g_rz[tid]    = 0.f;
    if (tid < NSYNC)        g_cnt[tid]   = 0u;
}

__global__ void scatter_k(const int* __restrict__ row, const int* __restrict__ col,
                          const float* __restrict__ val, int nnz){
    int e = blockIdx.x * blockDim.x + threadIdx.x;
    if (e >= nnz) return;
    int r = row[e];
    int d = col[e] - r;
    int slot;
    if      (d == 0)    slot = 0;
    else if (d == -256) slot = 1;
    else if (d == 256)  slot = 2;
    else if (d == -1)   slot = 3;
    else if (d == 1)    slot = 4;
    else if (d == -257) slot = 5;
    else if (d == 257)  slot = 6;
    else return;
    atomicAdd(&g_W[r*7 + slot], val[e]);
}

__device__ __forceinline__ float safe_log_neg(float u){
    float us = u;
    if (isnan(us))      us = 1e-9f;
    else if (isinf(us)) us = (us > 0.f) ? 1.0f : 0.0f;
    return -logf(fmaxf(us, 1e-9f));
}

// ---------------- persistent CG + post ----------------
__global__ void __launch_bounds__(NTHR, 1)
cg_persist(const float* __restrict__ M, const float* __restrict__ B,
           const float* __restrict__ tp,
           const int* __restrict__ F, const float* __restrict__ gI,
           const float* __restrict__ gJ, const float* __restrict__ gK,
           float* __restrict__ outU, float* __restrict__ outX, float* __restrict__ outS)
{
    const int v = blockIdx.x * NTHR + threadIdx.x;     // one vertex per thread
    const float t = *tp;

    float Dw = M[v] + t * g_W[v*7];
    float Minv = 1.0f / fmaxf(Dw, 1e-12f);
    float offW[6];
    #pragma unroll
    for (int e = 0; e < 6; e++) offW[e] = t * g_W[v*7 + 1 + e];

    float4 X[4], R[4], P[4], AP[4], Zo[4], s[4];
    const float4* B4 = (const float4*)B;
    #pragma unroll
    for (int j = 0; j < 4; j++){
        R[j]  = B4[v*4 + j];
        X[j]  = make_float4(0.f,0.f,0.f,0.f);
        P[j]  = make_float4(0.f,0.f,0.f,0.f);
        AP[j] = make_float4(0.f,0.f,0.f,0.f);
        Zo[j] = f4scale(Minv, R[j]);
        __stcg(&g_Z[v*4 + j], Zo[j]);
        s[j]  = f4mul(R[j], Zo[j]);
    }
    reduce16(s, &g_rz[0]);
    gsync(0);

    const int off[6] = {-256, 256, -1, 1, -257, 257};

    for (int k = 0; k < ITERS; k++){
        // ---- phase 1: P = Z + beta*P ; AP = A*Z + beta*AP ; denom = <P,AP> ----
        #pragma unroll
        for (int j = 0; j < 4; j++){
            float4 beta;
            if (k == 0) beta = make_float4(0.f,0.f,0.f,0.f);
            else {
                float4 rn = __ldcg(((const float4*)&g_rz[k*16]) + j);
                float4 ro = __ldcg(((const float4*)&g_rz[(k-1)*16]) + j);
                beta = f4div_guard(rn, ro);
            }
            AP[j] = f4fma(beta, AP[j], f4scale(Dw, Zo[j]));
            P[j]  = f4fma(beta, P[j], Zo[j]);
        }
        #pragma unroll
        for (int e = 0; e < 6; e++){
            int nb = v + off[e];
            nb = max(0, min(NV-1, nb));      // absent-edge weight is exactly 0
            float w = offW[e];
            #pragma unroll
            for (int j = 0; j < 4; j++){
                float4 z = __ldcg(&g_Z[nb*4 + j]);
                AP[j] = f4fmas(w, z, AP[j]);
            }
        }
        #pragma unroll
        for (int j = 0; j < 4; j++) s[j] = f4mul(P[j], AP[j]);
        reduce16(s, &g_denom[k*16]);
        gsync(1 + 2*k);

        // ---- phase 2: alpha ; X += aP ; R -= aAP ; Z = Minv*R ; rz_new = <R,Z> ----
        #pragma unroll
        for (int j = 0; j < 4; j++){
            float4 rz = __ldcg(((const float4*)&g_rz[k*16]) + j);
            float4 dn = __ldcg(((const float4*)&g_denom[k*16]) + j);
            float4 a  = f4div_guard(rz, dn);
            X[j] = f4fma(a, P[j], X[j]);
            float4 na = make_float4(-a.x,-a.y,-a.z,-a.w);
            R[j] = f4fma(na, AP[j], R[j]);
            Zo[j] = f4scale(Minv, R[j]);
            __stcg(&g_Z[v*4 + j], Zo[j]);
            s[j] = f4mul(R[j], Zo[j]);
        }
        reduce16(s, &g_rz[(k+1)*16]);
        gsync(2 + 2*k);
    }

    // ---- write U and S ----
    float4* oU = (float4*)outU;
    float4* oS = (float4*)outS;
    #pragma unroll
    for (int j = 0; j < 4; j++){
        __stcg(&oU[v*4 + j], X[j]);
        oS[v*4 + j] = make_float4(safe_log_neg(X[j].x), safe_log_neg(X[j].y),
                                  safe_log_neg(X[j].z), safe_log_neg(X[j].w));
    }
    gsync(81);

    // ---- faces: Xdir ----
    for (int f = v; f < NF; f += NV){
        int vi = F[f*3], vj = F[f*3+1], vk = F[f*3+2];
        float gix = gI[f*3], giy = gI[f*3+1], giz = gI[f*3+2];
        float gjx = gJ[f*3], gjy = gJ[f*3+1], gjz = gJ[f*3+2];
        float gkx = gK[f*3], gky = gK[f*3+1], gkz = gK[f*3+2];
        float* o = outX + f*48;
        #pragma unroll
        for (int j = 0; j < 4; j++){
            float4 uI = __ldcg(&oU[vi*4 + j]);
            float4 uJ = __ldcg(&oU[vj*4 + j]);
            float4 uK = __ldcg(&oU[vk*4 + j]);
            const float ui[4] = {uI.x, uI.y, uI.z, uI.w};
            const float uj[4] = {uJ.x, uJ.y, uJ.z, uJ.w};
            const float uk[4] = {uK.x, uK.y, uK.z, uK.w};
            #pragma unroll
            for (int c = 0; c < 4; c++){
                float gx = ui[c]*gix + uj[c]*gjx + uk[c]*gkx;
                float gy = ui[c]*giy + uj[c]*gjy + uk[c]*gky;
                float gz = ui[c]*giz + uj[c]*gjz + uk[c]*gkz;
                float n = sqrtf(gx*gx + gy*gy + gz*gz);
                n = fmaxf(n, 1e-12f);
                float inv = -1.0f / n;
                int cc = j*4 + c;
                o[cc*3+0] = gx*inv;
                o[cc*3+1] = gy*inv;
                o[cc*3+2] = gz*inv;
            }
        }
    }
}

extern "C" void kernel_launch(void* const* d_in, const int* in_sizes, int n_in,
                              void* d_out, int out_size) {
    const int*   F   = (const int*)  d_in[0];
    const int*   row = (const int*)  d_in[1];
    const int*   col = (const int*)  d_in[2];
    const float* val = (const float*)d_in[3];
    const float* M   = (const float*)d_in[4];
    const float* gI  = (const float*)d_in[5];
    const float* gJ  = (const float*)d_in[6];
    const float* gK  = (const float*)d_in[7];
    const float* B   = (const float*)d_in[8];
    const float* tp  = (const float*)d_in[9];
    int nnz = in_sizes[1];

    float* out  = (float*)d_out;
    float* outU = out;
    float* outX = out + NV*16;
    float* outS = out + NV*16 + NF*16*3;

    zero_k   <<<(NV*7)/256, 256>>>();
    scatter_k<<<(nnz + 255)/256, 256>>>(row, col, val, nnz);
    cg_persist<<<NBLK, NTHR>>>(M, B, tp, F, gI, gJ, gK, outU, outX, outS);
}

// round 3
// speedup vs baseline: 1.4042x; 1.4042x over previous
#include <cuda_runtime.h>
#include <math.h>

#define NV    65536
#define ITERS 40
#define NF    130050
#define NBLK  256
#define NTHR  512
#define NSYNC 96

// ---- device scratch (no allocations allowed) ----
__device__ __align__(16) float    g_W[NV*7];          // aggregated COO weights (slot 0 = diag)
__device__ __align__(16) float4   g_Z[NV*4];          // Z = Minv*R  (stencil operand)
__device__ __align__(16) float    g_denom[ITERS*16];
__device__ __align__(16) float    g_rz[(ITERS+1)*16];
__device__ unsigned               g_cnt[NSYNC];

// ---------------- helpers ----------------
__device__ __forceinline__ float4 f4mul(float4 a, float4 b){ return make_float4(a.x*b.x,a.y*b.y,a.z*b.z,a.w*b.w); }
__device__ __forceinline__ float4 f4fma(float4 a, float4 b, float4 c){
    return make_float4(fmaf(a.x,b.x,c.x), fmaf(a.y,b.y,c.y), fmaf(a.z,b.z,c.z), fmaf(a.w,b.w,c.w));
}
__device__ __forceinline__ float4 f4fmas(float s, float4 b, float4 c){
    return make_float4(fmaf(s,b.x,c.x), fmaf(s,b.y,c.y), fmaf(s,b.z,c.z), fmaf(s,b.w,c.w));
}
__device__ __forceinline__ float4 f4scale(float s, float4 a){ return make_float4(s*a.x,s*a.y,s*a.z,s*a.w); }
__device__ __forceinline__ float4 f4div_guard(float4 n, float4 d){
    return make_float4(n.x/fmaxf(d.x,1e-30f), n.y/fmaxf(d.y,1e-30f),
                       n.z/fmaxf(d.z,1e-30f), n.w/fmaxf(d.w,1e-30f));
}

// software grid barrier: per-index monotone counters, zeroed each launch by zero_k
__device__ __forceinline__ void gsync(int idx){
    __syncthreads();
    if (threadIdx.x == 0){
        __threadfence();
        atomicAdd(&g_cnt[idx], 1u);
        while (*(volatile unsigned*)&g_cnt[idx] < (unsigned)NBLK) { }
        __threadfence();
    }
    __syncthreads();
}

// Block reduce: each thread holds 8 partials (s[0..1]) for RHS range h*8..h*8+7,
// where h == (lane & 1). Accumulate into dst[0..15] with atomics.
__device__ __forceinline__ void reduce16(float4* s, float* dst){
    #pragma unroll
    for (int m = 2; m < 32; m <<= 1){
        #pragma unroll
        for (int j = 0; j < 2; j++){
            s[j].x += __shfl_xor_sync(0xffffffffu, s[j].x, m);
            s[j].y += __shfl_xor_sync(0xffffffffu, s[j].y, m);
            s[j].z += __shfl_xor_sync(0xffffffffu, s[j].z, m);
            s[j].w += __shfl_xor_sync(0xffffffffu, s[j].w, m);
        }
    }
    __shared__ float sm[16][16];
    int lane = threadIdx.x & 31, wid = threadIdx.x >> 5;
    if (lane < 2){                       // lane0 -> RHS 0..7, lane1 -> RHS 8..15
        float* row = &sm[wid][lane*8];
        row[0] = s[0].x; row[1] = s[0].y; row[2] = s[0].z; row[3] = s[0].w;
        row[4] = s[1].x; row[5] = s[1].y; row[6] = s[1].z; row[7] = s[1].w;
    }
    __syncthreads();
    if (threadIdx.x < 16){
        float acc = 0.f;
        #pragma unroll
        for (int w = 0; w < 16; w++) acc += sm[w][threadIdx.x];
        atomicAdd(&dst[threadIdx.x], acc);
    }
}

// ---------------- setup kernels ----------------
__global__ void zero_k(){
    int tid = blockIdx.x * blockDim.x + threadIdx.x;   // grid sized to exactly NV*7
    g_W[tid] = 0.f;
    if (tid < ITERS*16)     g_denom[tid] = 0.f;
    if (tid < (ITERS+1)*16) g_rz[tid]    = 0.f;
    if (tid < NSYNC)        g_cnt[tid]   = 0u;
}

__global__ void scatter_k(const int* __restrict__ row, const int* __restrict__ col,
                          const float* __restrict__ val, int nnz){
    int e = blockIdx.x * blockDim.x + threadIdx.x;
    if (e >= nnz) return;
    int r = row[e];
    int d = col[e] - r;
    int slot;
    if      (d == 0)    slot = 0;
    else if (d == -256) slot = 1;
    else if (d == 256)  slot = 2;
    else if (d == -1)   slot = 3;
    else if (d == 1)    slot = 4;
    else if (d == -257) slot = 5;
    else if (d == 257)  slot = 6;
    else return;
    atomicAdd(&g_W[r*7 + slot], val[e]);
}

__device__ __forceinline__ float safe_log_neg(float u){
    float us = u;
    if (isnan(us))      us = 1e-9f;
    else if (isinf(us)) us = (us > 0.f) ? 1.0f : 0.0f;
    return -logf(fmaxf(us, 1e-9f));
}

// ---------------- persistent CG + post ----------------
// 2 threads per vertex: h = tid&1 owns RHS [h*8, h*8+8)
__global__ void __launch_bounds__(NTHR, 2)
cg_persist(const float* __restrict__ M, const float* __restrict__ B,
           const float* __restrict__ tp,
           const int* __restrict__ F, const float* __restrict__ gI,
           const float* __restrict__ gJ, const float* __restrict__ gK,
           float* __restrict__ outU, float* __restrict__ outX, float* __restrict__ outS)
{
    const int tid = blockIdx.x * NTHR + threadIdx.x;   // [0, NV*2)
    const int v = tid >> 1;
    const int h = tid & 1;
    const int jb = h * 2;                              // float4 index base within [0,4)
    const float t = *tp;

    float Dw = M[v] + t * g_W[v*7];
    float Minv = 1.0f / fmaxf(Dw, 1e-12f);
    float offW[6];
    #pragma unroll
    for (int e = 0; e < 6; e++) offW[e] = t * g_W[v*7 + 1 + e];

    float4 X[2], R[2], P[2], AP[2], s[2];
    const float4* B4 = (const float4*)B;
    #pragma unroll
    for (int j = 0; j < 2; j++){
        R[j]  = B4[v*4 + jb + j];
        X[j]  = make_float4(0.f,0.f,0.f,0.f);
        P[j]  = make_float4(0.f,0.f,0.f,0.f);
        AP[j] = make_float4(0.f,0.f,0.f,0.f);
        float4 z = f4scale(Minv, R[j]);
        __stcg(&g_Z[v*4 + jb + j], z);
        s[j]  = f4mul(R[j], z);
    }
    reduce16(s, &g_rz[0]);
    gsync(0);

    const int off[6] = {-256, 256, -1, 1, -257, 257};

    for (int k = 0; k < ITERS; k++){
        // ---- phase 1: P = Z + beta*P ; AP = A*Z + beta*AP ; denom = <P,AP> ----
        {
            float4 z0 = __ldcg(&g_Z[v*4 + jb]);
            float4 z1 = __ldcg(&g_Z[v*4 + jb + 1]);
            if (k == 0){
                AP[0] = f4scale(Dw, z0);  AP[1] = f4scale(Dw, z1);
                P[0]  = z0;               P[1]  = z1;
            } else {
                const float* rzk  = &g_rz[k*16]     + h*8;
                const float* rzkm = &g_rz[(k-1)*16] + h*8;
                float4 bt0 = f4div_guard(*(const float4*)rzk,       *(const float4*)rzkm);
                float4 bt1 = f4div_guard(*(const float4*)(rzk + 4), *(const float4*)(rzkm + 4));
                AP[0] = f4fma(bt0, AP[0], f4scale(Dw, z0));
                AP[1] = f4fma(bt1, AP[1], f4scale(Dw, z1));
                P[0]  = f4fma(bt0, P[0], z0);
                P[1]  = f4fma(bt1, P[1], z1);
            }
        }
        #pragma unroll
        for (int e = 0; e < 6; e++){
            int nb = v + off[e];
            nb = max(0, min(NV-1, nb));      // absent-edge weight is exactly 0
            float w = offW[e];
            float4 z0 = __ldcg(&g_Z[nb*4 + jb]);
            float4 z1 = __ldcg(&g_Z[nb*4 + jb + 1]);
            AP[0] = f4fmas(w, z0, AP[0]);
            AP[1] = f4fmas(w, z1, AP[1]);
        }
        s[0] = f4mul(P[0], AP[0]);
        s[1] = f4mul(P[1], AP[1]);
        reduce16(s, &g_denom[k*16]);
        gsync(1 + 2*k);

        // ---- phase 2: alpha ; X += aP ; R -= aAP ; Z = Minv*R ; rz_new = <R,Z> ----
        {
            const float* rzk = &g_rz[k*16]    + h*8;
            const float* dnk = &g_denom[k*16] + h*8;
            #pragma unroll
            for (int j = 0; j < 2; j++){
                float4 a = f4div_guard(*(const float4*)(rzk + 4*j), *(const float4*)(dnk + 4*j));
                X[j] = f4fma(a, P[j], X[j]);
                float4 na = make_float4(-a.x,-a.y,-a.z,-a.w);
                R[j] = f4fma(na, AP[j], R[j]);
                float4 z = f4scale(Minv, R[j]);
                __stcg(&g_Z[v*4 + jb + j], z);
                s[j] = f4mul(R[j], z);
            }
        }
        reduce16(s, &g_rz[(k+1)*16]);
        gsync(2 + 2*k);
    }

    // ---- write U and S ----
    float4* oU = (float4*)outU;
    float4* oS = (float4*)outS;
    #pragma unroll
    for (int j = 0; j < 2; j++){
        __stcg(&oU[v*4 + jb + j], X[j]);
        oS[v*4 + jb + j] = make_float4(safe_log_neg(X[j].x), safe_log_neg(X[j].y),
                                       safe_log_neg(X[j].z), safe_log_neg(X[j].w));
    }
    gsync(81);

    // ---- faces: Xdir (one face per thread, full 16 RHS) ----
    for (int f = tid; f < NF; f += NV*2){
        int vi = F[f*3], vj = F[f*3+1], vk = F[f*3+2];
        float gix = gI[f*3], giy = gI[f*3+1], giz = gI[f*3+2];
        float gjx = gJ[f*3], gjy = gJ[f*3+1], gjz = gJ[f*3+2];
        float gkx = gK[f*3], gky = gK[f*3+1], gkz = gK[f*3+2];
        float* o = outX + f*48;
        #pragma unroll
        for (int j = 0; j < 4; j++){
            float4 uI = __ldcg(&oU[vi*4 + j]);
            float4 uJ = __ldcg(&oU[vj*4 + j]);
            float4 uK = __ldcg(&oU[vk*4 + j]);
            const float ui[4] = {uI.x, uI.y, uI.z, uI.w};
            const float uj[4] = {uJ.x, uJ.y, uJ.z, uJ.w};
            const float uk[4] = {uK.x, uK.y, uK.z, uK.w};
            #pragma unroll
            for (int c = 0; c < 4; c++){
                float gx = ui[c]*gix + uj[c]*gjx + uk[c]*gkx;
                float gy = ui[c]*giy + uj[c]*gjy + uk[c]*gky;
                float gz = ui[c]*giz + uj[c]*gjz + uk[c]*gkz;
                float n = sqrtf(gx*gx + gy*gy + gz*gz);
                n = fmaxf(n, 1e-12f);
                float inv = -1.0f / n;
                int cc = j*4 + c;
                o[cc*3+0] = gx*inv;
                o[cc*3+1] = gy*inv;
                o[cc*3+2] = gz*inv;
            }
        }
    }
}

extern "C" void kernel_launch(void* const* d_in, const int* in_sizes, int n_in,
                              void* d_out, int out_size) {
    const int*   F   = (const int*)  d_in[0];
    const int*   row = (const int*)  d_in[1];
    const int*   col = (const int*)  d_in[2];
    const float* val = (const float*)d_in[3];
    const float* M   = (const float*)d_in[4];
    const float* gI  = (const float*)d_in[5];
    const float* gJ  = (const float*)d_in[6];
    const float* gK  = (const float*)d_in[7];
    const float* B   = (const float*)d_in[8];
    const float* tp  = (const float*)d_in[9];
    int nnz = in_sizes[1];

    float* out  = (float*)d_out;
    float* outU = out;
    float* outX = out + NV*16;
    float* outS = out + NV*16 + NF*16*3;

    zero_k   <<<(NV*7)/256, 256>>>();
    scatter_k<<<(nnz + 255)/256, 256>>>(row, col, val, nnz);
    cg_persist<<<NBLK, NTHR>>>(M, B, tp, F, gI, gJ, gK, outU, outX, outS);
}